// round 1
// baseline (speedup 1.0000x reference)
#include <cuda_runtime.h>

// ---------------------------------------------------------------------------
// MomGRU adding-problem: persistent fused recurrence kernel.
// Grid = 128 CTAs (8 batch-blocks x 16 hidden-blocks), 128 threads each,
// single wave on 148 SMs. W_hh slice splatted to float2 in SMEM; inner GEMM
// uses packed fma.rn.f32x2 (2 batch elements per FMA). Per-step grid-wide
// barrier via global atomics (monotonic generation -> graph-replay safe).
// ---------------------------------------------------------------------------

namespace {
constexpr int BATCH = 128;
constexpr int SEQ   = 1024;
constexpr int HID   = 256;
constexpr int GB    = 8;            // batch blocks
constexpr int GH    = 16;           // hidden blocks
constexpr int NCTA  = GB * GH;      // 128
constexpr int BB    = BATCH / GB;   // 16 batches per CTA
constexpr int NBP   = BB / 2;       // 8 batch pairs
constexpr int UPC   = HID / GH;     // 16 hidden units per CTA
constexpr int NROWS = 3 * UPC;      // 48 W_hh rows per CTA
constexpr int NTH   = 128;
constexpr int KP    = HID + 2;      // padded row length (float2 units) -> bank-conflict-free

// dynamic smem layout (in floats)
constexpr int OFF_W2   = 0;                          // NROWS*KP float2
constexpr int OFF_H2   = OFF_W2 + NROWS * KP * 2;    // NBP*KP float2
constexpr int OFF_WIH  = OFF_H2 + NBP * KP * 2;      // NROWS float2
constexpr int OFF_BIH  = OFF_WIH + NROWS * 2;        // NROWS
constexpr int OFF_BHH  = OFF_BIH + NROWS;            // NROWS
constexpr int OFF_WBH  = OFF_BHH + NROWS;            // HID
constexpr int OFF_WHD  = OFF_WBH + HID;              // HID
constexpr int OFF_BETA = OFF_WHD + HID;              // BB
constexpr int OFF_XS   = OFF_BETA + BB;              // BB float2
constexpr int OFF_RED  = OFF_XS + BB * 2;            // UPC*NBP float2
constexpr int OFF_SCAL = OFF_RED + UPC * NBP * 2;    // 8
constexpr int SMEM_FLOATS = OFF_SCAL + 8;
constexpr int SMEM_BYTES  = SMEM_FLOATS * 4;         // ~119.7 KB
}

// persistent device state (allowed: no runtime allocation)
__device__ float    g_h[2][HID][BATCH];
__device__ unsigned g_count;
__device__ unsigned g_release;

// ---- packed fp32x2 helpers -------------------------------------------------
__device__ __forceinline__ unsigned long long pk2(float2 v) {
    unsigned long long r;
    asm("mov.b64 %0, {%1,%2};" : "=l"(r) : "f"(v.x), "f"(v.y));
    return r;
}
__device__ __forceinline__ float2 upk2(unsigned long long v) {
    float2 r;
    asm("mov.b64 {%0,%1}, %2;" : "=f"(r.x), "=f"(r.y) : "l"(v));
    return r;
}
__device__ __forceinline__ float2 ffma2(float2 a, float2 b, float2 c) {
    unsigned long long d;
    asm("fma.rn.f32x2 %0, %1, %2, %3;"
        : "=l"(d) : "l"(pk2(a)), "l"(pk2(b)), "l"(pk2(c)));
    return upk2(d);
}

__device__ __forceinline__ float sigf(float x) {
    return 1.0f / (1.0f + __expf(-x));
}
__device__ __forceinline__ float tanh_fast(float x) {
    float ax = fabsf(x);
    float e  = __expf(-2.0f * ax);
    float t  = (1.0f - e) / (1.0f + e);
    return copysignf(t, x);
}

// grid-wide barrier: sense via monotonic generation counter
__device__ __forceinline__ void grid_barrier(unsigned target) {
    __syncthreads();
    if (threadIdx.x == 0) {
        __threadfence();
        unsigned a = atomicAdd(&g_count, 1u);
        if (a == (unsigned)(NCTA - 1)) {
            atomicExch(&g_count, 0u);
            __threadfence();
            atomicExch(&g_release, target);
        } else {
            while ((int)(*(volatile unsigned*)&g_release - target) < 0) { }
        }
        __threadfence();
    }
    __syncthreads();
}

extern "C" __global__ void __launch_bounds__(NTH, 1)
momgru_kernel(const float* __restrict__ x,
              const float* __restrict__ W_ih,
              const float* __restrict__ W_hh,
              const float* __restrict__ b_ih,
              const float* __restrict__ b_hh,
              const float* __restrict__ Wb_x,
              const float* __restrict__ Wb_h,
              const float* __restrict__ b_beta,
              const float* __restrict__ s_ptr,
              const float* __restrict__ W_head,
              const float* __restrict__ b_head,
              float* __restrict__ out)
{
    extern __shared__ float smem[];
    float2* w2     = (float2*)(smem + OFF_W2);
    float2* h2     = (float2*)(smem + OFF_H2);
    float2* wih    = (float2*)(smem + OFF_WIH);
    float*  bih    = smem + OFF_BIH;
    float*  bhh    = smem + OFF_BHH;
    float*  wbh    = smem + OFF_WBH;
    float*  whd    = smem + OFF_WHD;
    float*  beta_s = smem + OFF_BETA;
    float2* xs     = (float2*)(smem + OFF_XS);
    float2* red    = (float2*)(smem + OFF_RED);
    float*  scal   = smem + OFF_SCAL;

    const int tid = threadIdx.x;
    const int j   = blockIdx.x % GH;   // hidden block
    const int i   = blockIdx.x / GH;   // batch block
    const int b0  = i * BB;
    const int u0  = j * UPC;
    const int bp  = tid & (NBP - 1);   // 0..7  batch pair
    const int u   = tid >> 3;          // 0..15 hidden unit (local)

    // ---- one-time weight preload -------------------------------------------
    for (int e = tid; e < NROWS * HID; e += NTH) {
        int row = e >> 8;           // /HID
        int k   = e & (HID - 1);
        int g   = row >> 4;         // /UPC
        int uu  = row & (UPC - 1);
        float w = W_hh[(g * HID + u0 + uu) * HID + k];
        w2[row * KP + k] = make_float2(w, w);     // pre-splatted for f32x2
    }
    if (tid < NROWS) {
        int g  = tid >> 4;
        int uu = tid & (UPC - 1);
        int gr = g * HID + u0 + uu;
        wih[tid] = make_float2(W_ih[gr * 2 + 0], W_ih[gr * 2 + 1]);
        bih[tid] = b_ih[gr];
        bhh[tid] = b_hh[gr];
    }
    for (int e = tid; e < HID; e += NTH) {
        wbh[e] = Wb_h[e];
        whd[e] = W_head[e];
    }
    if (tid == 0) {
        scal[0] = Wb_x[0];
        scal[1] = Wb_x[1];
        scal[2] = b_beta[0];
        scal[3] = s_ptr[0];
        scal[4] = b_head[0];
        // launch-stable base generation of the global barrier
        scal[5] = __uint_as_float(*(volatile unsigned*)&g_release);
    }
    // zero h0 (each CTA zeroes a disjoint 256-float slice of g_h[0])
    {
        float* gz = &g_h[0][0][0];
        int base  = blockIdx.x * (HID * BATCH / NCTA);   // 256 floats
        gz[base + tid]       = 0.0f;
        gz[base + NTH + tid] = 0.0f;
    }
    __syncthreads();

    const float wbx0  = scal[0];
    const float wbx1  = scal[1];
    const float bbeta = scal[2];
    const float sv    = scal[3];
    const float bhead = scal[4];
    const unsigned R0 = __float_as_uint(scal[5]);

    const float2 wihr = wih[u];
    const float2 wihz = wih[UPC + u];
    const float2 wihn = wih[2 * UPC + u];
    const float  bihr = bih[u],        bihz = bih[UPC + u],       bihn = bih[2 * UPC + u];
    const float  bhhr = bhh[u],        bhhz = bhh[UPC + u],       bhhn = bhh[2 * UPC + u];

    const float2* wr  = w2 + (u)            * KP;
    const float2* wzp = w2 + (UPC + u)      * KP;
    const float2* wnp = w2 + (2 * UPC + u)  * KP;
    const float2* hp  = h2 + bp * KP;

    unsigned tgt = R0 + 1;
    grid_barrier(tgt);                        // h0 zero visible everywhere

    float2 vr = make_float2(0.f, 0.f);
    float2 vz = make_float2(0.f, 0.f);
    float2 vn = make_float2(0.f, 0.f);

    for (int t = 0; t < SEQ; ++t) {
        // ---- load this CTA's 16 h rows (L2-only; L1 would be stale) --------
        const float* hsrc = &g_h[t & 1][0][0];
        #pragma unroll
        for (int n = 0; n < 8; ++n) {
            int e = n * NTH + tid;        // 0..1023
            int k = e >> 2;
            int q = e & 3;
            float4 hv = __ldcg((const float4*)(hsrc + k * BATCH + b0 + 4 * q));
            h2[(2 * q)     * KP + k] = make_float2(hv.x, hv.y);
            h2[(2 * q + 1) * KP + k] = make_float2(hv.z, hv.w);
        }
        __syncthreads();

        // ---- beta partial dot: h . Wb_h (per batch pair, split over u) -----
        {
            float2 pb = make_float2(0.f, 0.f);
            const float*  wb = wbh + u * 16;
            const float2* hq = hp  + u * 16;
            #pragma unroll
            for (int m = 0; m < 16; ++m) {
                float w = wb[m];
                pb = ffma2(make_float2(w, w), hq[m], pb);
            }
            red[u * NBP + bp] = pb;
        }
        __syncthreads();

        if (tid < BB) {
            int b = tid;
            float acc = 0.f;
            #pragma unroll
            for (int m = 0; m < UPC; ++m) {
                float2 v = red[m * NBP + (b >> 1)];
                acc += (b & 1) ? v.y : v.x;
            }
            float2 xv = __ldg(((const float2*)x) + (b0 + b) * SEQ + t);
            float bval = sigf(xv.x * wbx0 + xv.y * wbx1 + acc + bbeta);
            beta_s[b] = bval;
            xs[b]     = xv;
            if (j == 0) out[BATCH + (b0 + b) * SEQ + t] = bval;   // betas[b][t]
        }
        __syncthreads();

        // ---- momentum buffer update: v = beta*v + s*(x W_ih^T + b_ih) ------
        const float2 be = *(const float2*)&beta_s[2 * bp];
        const float2 xa = xs[2 * bp];
        const float2 xb = xs[2 * bp + 1];
        {
            float pa = xa.x * wihr.x + xa.y * wihr.y + bihr;
            float pb = xb.x * wihr.x + xb.y * wihr.y + bihr;
            vr = ffma2(be, vr, make_float2(sv * pa, sv * pb));
            pa = xa.x * wihz.x + xa.y * wihz.y + bihz;
            pb = xb.x * wihz.x + xb.y * wihz.y + bihz;
            vz = ffma2(be, vz, make_float2(sv * pa, sv * pb));
            pa = xa.x * wihn.x + xa.y * wihn.y + bihn;
            pb = xb.x * wihn.x + xb.y * wihn.y + bihn;
            vn = ffma2(be, vn, make_float2(sv * pa, sv * pb));
        }

        // ---- gh = h @ W_hh^T + b_hh : packed f32x2 GEMM over K=256 ---------
        float2 ar = make_float2(bhhr, bhhr);
        float2 az = make_float2(bhhz, bhhz);
        float2 an = make_float2(bhhn, bhhn);
        #pragma unroll 8
        for (int k = 0; k < HID; k += 2) {
            float4 hv4 = *(const float4*)(hp  + k);
            float4 w0  = *(const float4*)(wr  + k);
            float4 w1  = *(const float4*)(wzp + k);
            float4 w2v = *(const float4*)(wnp + k);
            float2 ha = make_float2(hv4.x, hv4.y);
            float2 hb = make_float2(hv4.z, hv4.w);
            ar = ffma2(make_float2(w0.x,  w0.y),  ha, ar);
            az = ffma2(make_float2(w1.x,  w1.y),  ha, az);
            an = ffma2(make_float2(w2v.x, w2v.y), ha, an);
            ar = ffma2(make_float2(w0.z,  w0.w),  hb, ar);
            az = ffma2(make_float2(w1.z,  w1.w),  hb, az);
            an = ffma2(make_float2(w2v.z, w2v.w), hb, an);
        }

        // ---- gates & state update ------------------------------------------
        float2 hprev = hp[u0 + u];
        float ra = sigf(vr.x + ar.x), rb = sigf(vr.y + ar.y);
        float za = sigf(vz.x + az.x), zb = sigf(vz.y + az.y);
        float na = tanh_fast(vn.x + ra * an.x);
        float nb = tanh_fast(vn.y + rb * an.y);
        float hna = (1.0f - za) * na + za * hprev.x;
        float hnb = (1.0f - zb) * nb + zb * hprev.y;

        float* hdst = &g_h[(t + 1) & 1][0][0];
        __stcg((float2*)(hdst + (u0 + u) * BATCH + b0 + 2 * bp),
               make_float2(hna, hnb));

        ++tgt;
        grid_barrier(tgt);
    }

    // ---- head: out[b] = h_T . W_head + b_head (h_T in g_h[0]) --------------
    if (j == 0) {
        int b   = tid >> 3;
        int sub = tid & 7;
        const float* hT = &g_h[0][0][0];
        float acc = 0.f;
        #pragma unroll
        for (int m = 0; m < 32; ++m) {
            int k = sub + 8 * m;
            acc += __ldcg(hT + k * BATCH + b0 + b) * whd[k];
        }
        acc += __shfl_xor_sync(0xffffffffu, acc, 4);
        acc += __shfl_xor_sync(0xffffffffu, acc, 2);
        acc += __shfl_xor_sync(0xffffffffu, acc, 1);
        if (sub == 0) out[b0 + b] = acc + bhead;
    }
}

extern "C" void kernel_launch(void* const* d_in, const int* in_sizes, int n_in,
                              void* d_out, int out_size) {
    const float* x      = (const float*)d_in[0];
    const float* W_ih   = (const float*)d_in[1];
    const float* W_hh   = (const float*)d_in[2];
    const float* b_ih   = (const float*)d_in[3];
    const float* b_hh   = (const float*)d_in[4];
    const float* Wb_x   = (const float*)d_in[5];
    const float* Wb_h   = (const float*)d_in[6];
    const float* b_beta = (const float*)d_in[7];
    const float* s      = (const float*)d_in[8];
    const float* W_head = (const float*)d_in[9];
    const float* b_head = (const float*)d_in[10];

    // dynamic smem > 48KB needs the attribute; idempotent, capture-safe
    cudaFuncSetAttribute(momgru_kernel,
                         cudaFuncAttributeMaxDynamicSharedMemorySize,
                         SMEM_BYTES);

    momgru_kernel<<<NCTA, NTH, SMEM_BYTES>>>(
        x, W_ih, W_hh, b_ih, b_hh, Wb_x, Wb_h, b_beta, s, W_head, b_head,
        (float*)d_out);
}

// round 2
// speedup vs baseline: 1.3197x; 1.3197x over previous
#include <cuda_runtime.h>

// ---------------------------------------------------------------------------
// MomGRU persistent recurrence, round 2.
// Grid 128 CTAs = 16 batch-blocks x 8 hidden-blocks; cluster(8) groups the 8
// hidden-block CTAs of one batch block (the only CTAs that must synchronize).
// 256 threads/CTA: thread = (u 0..31, bq 0..1, ks 0..3); K split 4-way with
// shfl.bfly reduction. f32x2 FMAs vectorize over K (no weight duplication).
// h exchanged through L2 (stcg/ldcg) under cluster arrive/wait (rel/acq).
// ---------------------------------------------------------------------------

namespace {
constexpr int BATCH = 128;
constexpr int SEQ   = 1024;
constexpr int HID   = 256;
constexpr int GB    = 16;              // batch blocks
constexpr int GH    = 8;               // hidden blocks (= cluster size)
constexpr int NCTA  = GB * GH;         // 128
constexpr int BB    = BATCH / GB;      // 8 batches per CTA
constexpr int UPC   = HID / GH;        // 32 hidden units per CTA
constexpr int NROWS = 3 * UPC;         // 96 W_hh rows per CTA
constexpr int NTH   = 256;
constexpr int RSW   = HID + 16;        // 272: row stride (floats), mod32=16 -> 2-phase LDS
constexpr int RSH   = HID + 4;         // 260: h row stride, 4*260 mod32=16 -> 1-phase LDS

// smem layout (floats)
constexpr int OFF_W   = 0;                       // NROWS * RSW
constexpr int OFF_H   = OFF_W + NROWS * RSW;     // BB * RSH
constexpr int OFF_WBH = OFF_H + BB * RSH;        // HID
constexpr int OFF_WHD = OFF_WBH + HID;           // HID
constexpr int OFF_BS  = OFF_WHD + HID;           // BB
constexpr int OFF_XS  = OFF_BS + BB;             // BB float2
constexpr int SMEM_FLOATS = OFF_XS + BB * 2;
constexpr int SMEM_BYTES  = SMEM_FLOATS * 4;     // ~114.9 KB
}

// persistent h ping-pong, layout [buf][batch][hid]
__device__ float g_h[2][BATCH][HID];

// ---- packed fp32x2 helpers -------------------------------------------------
__device__ __forceinline__ unsigned long long pk2(float2 v) {
    unsigned long long r;
    asm("mov.b64 %0, {%1,%2};" : "=l"(r) : "f"(v.x), "f"(v.y));
    return r;
}
__device__ __forceinline__ float2 upk2(unsigned long long v) {
    float2 r;
    asm("mov.b64 {%0,%1}, %2;" : "=f"(r.x), "=f"(r.y) : "l"(v));
    return r;
}
__device__ __forceinline__ float2 ffma2(float2 a, float2 b, float2 c) {
    unsigned long long d;
    asm("fma.rn.f32x2 %0, %1, %2, %3;"
        : "=l"(d) : "l"(pk2(a)), "l"(pk2(b)), "l"(pk2(c)));
    return upk2(d);
}

__device__ __forceinline__ float sigf(float x) {
    return 1.0f / (1.0f + __expf(-x));
}
__device__ __forceinline__ float tanh_fast(float x) {
    float ax = fabsf(x);
    float e  = __expf(-2.0f * ax);
    float t  = (1.0f - e) / (1.0f + e);
    return copysignf(t, x);
}

#define CLUSTER_ARRIVE() asm volatile("barrier.cluster.arrive.aligned;" ::: "memory")
#define CLUSTER_WAIT()   asm volatile("barrier.cluster.wait.aligned;"   ::: "memory")

extern "C" __global__ void __launch_bounds__(NTH, 1) __cluster_dims__(GH, 1, 1)
momgru_kernel(const float* __restrict__ x,
              const float* __restrict__ W_ih,
              const float* __restrict__ W_hh,
              const float* __restrict__ b_ih,
              const float* __restrict__ b_hh,
              const float* __restrict__ Wb_x,
              const float* __restrict__ Wb_h,
              const float* __restrict__ b_beta,
              const float* __restrict__ s_ptr,
              const float* __restrict__ W_head,
              const float* __restrict__ b_head,
              float* __restrict__ out)
{
    extern __shared__ float sm[];
    float*  ws     = sm + OFF_W;
    float*  hs     = sm + OFF_H;
    float*  wbhs   = sm + OFF_WBH;
    float*  whds   = sm + OFF_WHD;
    float*  beta_s = sm + OFF_BS;
    float2* xs     = (float2*)(sm + OFF_XS);

    const int tid = threadIdx.x;
    const int j   = blockIdx.x & (GH - 1);    // hidden block / cluster rank
    const int i   = blockIdx.x >> 3;          // batch block
    const int b0  = i * BB;
    const int u0  = j * UPC;

    const int u  = tid >> 3;        // 0..31  hidden unit (local)
    const int bq = (tid >> 2) & 1;  // 0..1   batch quad
    const int ks = tid & 3;         // 0..3   K-split lane
    const int bg = bq * 4 + ks;     // 0..7   this thread's gate-owned batch

    // ---- one-time preload ---------------------------------------------------
    for (int e = tid; e < NROWS * HID; e += NTH) {
        int row = e >> 8;
        int k   = e & (HID - 1);
        int g   = row >> 5;
        int uu  = row & 31;
        ws[row * RSW + k] = W_hh[(g * HID + u0 + uu) * HID + k];
    }
    for (int e = tid; e < HID; e += NTH) {
        wbhs[e] = Wb_h[e];
        whds[e] = W_head[e];
    }
    const float wbx0  = __ldg(Wb_x);
    const float wbx1  = __ldg(Wb_x + 1);
    const float bbeta = __ldg(b_beta);
    const float sv    = __ldg(s_ptr);
    const float bhead = __ldg(b_head);

    float2 wihg[3];
    float  bihg[3], bhhg[3];
    #pragma unroll
    for (int g = 0; g < 3; ++g) {
        int gr  = g * HID + u0 + u;
        wihg[g] = make_float2(__ldg(W_ih + gr * 2), __ldg(W_ih + gr * 2 + 1));
        bihg[g] = __ldg(b_ih + gr);
        bhhg[g] = __ldg(b_hh + gr);
    }

    // zero h0 for this CTA's (b,u) write region
    {
        int b  = tid >> 5;
        int uu = tid & 31;
        g_h[0][b0 + b][u0 + uu] = 0.0f;
    }
    CLUSTER_ARRIVE();   // release: h0 zeros visible to cluster after next wait

    // per-thread momentum state for (u, bg)
    float v0 = 0.f, v1 = 0.f, v2 = 0.f;

    // GEMM smem base pointers (K-interleaved: this thread's k = ks*4 + kk*16 + {0..3})
    const float* w0p = ws + (0 * UPC + u) * RSW + ks * 4;
    const float* w1p = ws + (1 * UPC + u) * RSW + ks * 4;
    const float* w2p = ws + (2 * UPC + u) * RSW + ks * 4;
    const float* h0p = hs + (bq * 4 + 0) * RSH + ks * 4;
    const float* h1p = hs + (bq * 4 + 1) * RSH + ks * 4;
    const float* h2p = hs + (bq * 4 + 2) * RSH + ks * 4;
    const float* h3p = hs + (bq * 4 + 3) * RSH + ks * 4;

    for (int t = 0; t < SEQ; ++t) {
        CLUSTER_WAIT();   // acquire: peers' h_t stores visible

        // prefetch x early (one lane per batch)
        float2 xv = make_float2(0.f, 0.f);
        const int bb = tid >> 3;     // beta batch (tid<64)
        const int kc = tid & 7;      // beta K-chunk lane
        if (tid < 64 && kc == 0)
            xv = __ldg((const float2*)x + (b0 + bb) * SEQ + t);

        // ---- load h_t -> smem [b][k] (coalesced float4 over L2) ------------
        const float* hsrc = &g_h[t & 1][b0][0];
        float4 hv0 = __ldcg((const float4*)hsrc + tid);
        float4 hv1 = __ldcg((const float4*)hsrc + NTH + tid);
        {
            int e = tid;
            *(float4*)(hs + (e >> 6) * RSH + (e & 63) * 4) = hv0;
            e = tid + NTH;
            *(float4*)(hs + (e >> 6) * RSH + (e & 63) * 4) = hv1;
        }
        __syncthreads();

        // ---- beta: h . Wb_h (warps 0-1 only; 8 batches x 8 k-chunks) -------
        if (tid < 64) {
            const float* hrow = hs + bb * RSH + kc * 4;
            const float* wrow = wbhs + kc * 4;
            float2 a2 = make_float2(0.f, 0.f);
            #pragma unroll
            for (int kk = 0; kk < 8; ++kk) {
                float4 h4 = *(const float4*)(hrow + kk * 32);
                float4 w4 = *(const float4*)(wrow + kk * 32);
                a2 = ffma2(make_float2(w4.x, w4.y), make_float2(h4.x, h4.y), a2);
                a2 = ffma2(make_float2(w4.z, w4.w), make_float2(h4.z, h4.w), a2);
            }
            float a = a2.x + a2.y;
            a += __shfl_xor_sync(0xffffffffu, a, 1);
            a += __shfl_xor_sync(0xffffffffu, a, 2);
            a += __shfl_xor_sync(0xffffffffu, a, 4);
            if (kc == 0) {
                float bval = sigf(xv.x * wbx0 + xv.y * wbx1 + a + bbeta);
                beta_s[bb] = bval;
                xs[bb]     = xv;
                if (j == 0) out[BATCH + (b0 + bb) * SEQ + t] = bval;
            }
        }

        // ---- gh = h @ W_hh^T : f32x2 over K, per-thread (3 gates x 4 b) ----
        float2 acc[3][4];
        #pragma unroll
        for (int g = 0; g < 3; ++g)
            #pragma unroll
            for (int bi = 0; bi < 4; ++bi) acc[g][bi] = make_float2(0.f, 0.f);

        #pragma unroll
        for (int kk = 0; kk < 16; ++kk) {
            const int o = kk * 16;
            float4 w4[3], h4[4];
            w4[0] = *(const float4*)(w0p + o);
            w4[1] = *(const float4*)(w1p + o);
            w4[2] = *(const float4*)(w2p + o);
            h4[0] = *(const float4*)(h0p + o);
            h4[1] = *(const float4*)(h1p + o);
            h4[2] = *(const float4*)(h2p + o);
            h4[3] = *(const float4*)(h3p + o);
            #pragma unroll
            for (int g = 0; g < 3; ++g)
                #pragma unroll
                for (int bi = 0; bi < 4; ++bi)
                    acc[g][bi] = ffma2(make_float2(w4[g].x, w4[g].y),
                                       make_float2(h4[bi].x, h4[bi].y), acc[g][bi]);
            #pragma unroll
            for (int g = 0; g < 3; ++g)
                #pragma unroll
                for (int bi = 0; bi < 4; ++bi)
                    acc[g][bi] = ffma2(make_float2(w4[g].z, w4[g].w),
                                       make_float2(h4[bi].z, h4[bi].w), acc[g][bi]);
        }

        // ---- K-split reduce (bfly over ks lanes -> full sum in all lanes) --
        float gsum[3][4];
        #pragma unroll
        for (int g = 0; g < 3; ++g)
            #pragma unroll
            for (int bi = 0; bi < 4; ++bi) {
                float sc = acc[g][bi].x + acc[g][bi].y;
                sc += __shfl_xor_sync(0xffffffffu, sc, 1);
                sc += __shfl_xor_sync(0xffffffffu, sc, 2);
                gsum[g][bi] = sc;
            }

        __syncthreads();   // beta_s / xs ready for all

        // ---- v update + gates: thread owns (u, batch bg = bq*4+ks) ---------
        {
            const float  be    = beta_s[bg];
            const float2 xv2   = xs[bg];
            const float  hprev = hs[bg * RSH + u0 + u];

            float pr = xv2.x * wihg[0].x + xv2.y * wihg[0].y + bihg[0];
            float pz = xv2.x * wihg[1].x + xv2.y * wihg[1].y + bihg[1];
            float pn = xv2.x * wihg[2].x + xv2.y * wihg[2].y + bihg[2];
            v0 = be * v0 + sv * pr;
            v1 = be * v1 + sv * pz;
            v2 = be * v2 + sv * pn;

            float ghr = gsum[0][ks] + bhhg[0];
            float ghz = gsum[1][ks] + bhhg[1];
            float ghn = gsum[2][ks] + bhhg[2];

            float r  = sigf(v0 + ghr);
            float z  = sigf(v1 + ghz);
            float n  = tanh_fast(v2 + r * ghn);
            float hn = (1.0f - z) * n + z * hprev;

            __stcg(&g_h[(t + 1) & 1][b0 + bg][u0 + u], hn);
        }

        CLUSTER_ARRIVE();  // release h_{t+1} stores
    }

    CLUSTER_WAIT();        // final h (buffer 0, SEQ even) visible

    // ---- head: out[b] = h_T . W_head + b_head (rank-0 CTA per batch block) -
    if (j == 0 && tid < 64) {
        int b  = tid >> 3;
        int kc = tid & 7;
        const float* hT = &g_h[0][b0 + b][0];
        float2 a2 = make_float2(0.f, 0.f);
        #pragma unroll
        for (int kk = 0; kk < 8; ++kk) {
            float4 h4 = __ldcg((const float4*)(hT + kc * 4 + kk * 32));
            float4 w4 = *(const float4*)(whds + kc * 4 + kk * 32);
            a2 = ffma2(make_float2(w4.x, w4.y), make_float2(h4.x, h4.y), a2);
            a2 = ffma2(make_float2(w4.z, w4.w), make_float2(h4.z, h4.w), a2);
        }
        float a = a2.x + a2.y;
        a += __shfl_xor_sync(0xffffffffu, a, 1);
        a += __shfl_xor_sync(0xffffffffu, a, 2);
        a += __shfl_xor_sync(0xffffffffu, a, 4);
        if (kc == 0) out[b0 + b] = a + bhead;
    }
}

extern "C" void kernel_launch(void* const* d_in, const int* in_sizes, int n_in,
                              void* d_out, int out_size) {
    const float* x      = (const float*)d_in[0];
    const float* W_ih   = (const float*)d_in[1];
    const float* W_hh   = (const float*)d_in[2];
    const float* b_ih   = (const float*)d_in[3];
    const float* b_hh   = (const float*)d_in[4];
    const float* Wb_x   = (const float*)d_in[5];
    const float* Wb_h   = (const float*)d_in[6];
    const float* b_beta = (const float*)d_in[7];
    const float* s      = (const float*)d_in[8];
    const float* W_head = (const float*)d_in[9];
    const float* b_head = (const float*)d_in[10];

    cudaFuncSetAttribute(momgru_kernel,
                         cudaFuncAttributeMaxDynamicSharedMemorySize,
                         SMEM_BYTES);

    momgru_kernel<<<NCTA, NTH, SMEM_BYTES>>>(
        x, W_ih, W_hh, b_ih, b_hh, Wb_x, Wb_h, b_beta, s, W_head, b_head,
        (float*)d_out);
}